// round 12
// baseline (speedup 1.0000x reference)
#include <cuda_runtime.h>
#include <cuda_fp16.h>
#include <math.h>
#include <stdint.h>

#define Bsz   2
#define Tsz   2048
#define Dsz   512
#define Hn    8
#define HDm   64
#define Kw    16
#define NDEPTH 3
#define ROWS  (Bsz*Tsz)   // 4096

// ---------------- scratch (static device globals; no allocation) ----------------
__device__ __half g_h[ROWS * Dsz];
__device__ __half g_qkv[ROWS * 3 * Dsz];
__device__ __half g_o[ROWS * Dsz];
__device__ __half g_mlp[ROWS * 4 * Dsz];
// transposed fp16 weights ([N,K], K contiguous)
__device__ __half g_qkvwT[NDEPTH * 3 * Dsz * Dsz];
__device__ __half g_projwT[NDEPTH * Dsz * Dsz];
__device__ __half g_w1T[NDEPTH * 4 * Dsz * Dsz];
__device__ __half g_w2T[NDEPTH * Dsz * 4 * Dsz];

// ---------------- helpers ----------------------------------------------------------
__device__ __forceinline__ uint32_t smem_u32(const void* p) {
    uint32_t a;
    asm("{ .reg .u64 t; cvta.to.shared.u64 t, %1; cvt.u32.u64 %0, t; }" : "=r"(a) : "l"(p));
    return a;
}
__device__ __forceinline__ void cp16(uint32_t s, const void* g) {
    asm volatile("cp.async.cg.shared.global [%0], [%1], 16;" :: "r"(s), "l"(g));
}
__device__ __forceinline__ void ldsm4(uint32_t* r, uint32_t addr) {
    asm volatile("ldmatrix.sync.aligned.m8n8.x4.shared.b16 {%0,%1,%2,%3}, [%4];"
                 : "=r"(r[0]), "=r"(r[1]), "=r"(r[2]), "=r"(r[3]) : "r"(addr));
}
__device__ __forceinline__ void mma_f16(float* c, const uint32_t* a, const uint32_t* b) {
    asm volatile(
        "mma.sync.aligned.m16n8k16.row.col.f32.f16.f16.f32 "
        "{%0,%1,%2,%3}, {%4,%5,%6,%7}, {%8,%9}, {%0,%1,%2,%3};"
        : "+f"(c[0]), "+f"(c[1]), "+f"(c[2]), "+f"(c[3])
        : "r"(a[0]), "r"(a[1]), "r"(a[2]), "r"(a[3]), "r"(b[0]), "r"(b[1]));
}

// ---------------- weight prep (split in two launches for profiling order) -----------
__device__ __forceinline__ void tr_tile(const float* in, __half* out, int R, int C, int t0) {
    __shared__ float tile[32][33];
    int tpc = C / 32;
    int r0 = (t0 / tpc) * 32, c0 = (t0 % tpc) * 32;
    int tx = threadIdx.x, ty = threadIdx.y;   // (32, 8)
    #pragma unroll
    for (int i = 0; i < 32; i += 8)
        tile[ty + i][tx] = in[(size_t)(r0 + ty + i) * C + c0 + tx];
    __syncthreads();
    #pragma unroll
    for (int i = 0; i < 32; i += 8)
        out[(size_t)(c0 + ty + i) * R + r0 + tx] = __float2half(tile[tx][ty + i]);
}

__global__ void prep_weights_a(const float* __restrict__ qkv_w, const float* __restrict__ proj_w) {
    int id = blockIdx.x;
    int d  = id / 1024;
    int r  = id % 1024;
    if (r < 768) tr_tile(qkv_w  + (size_t)d * Dsz * 3 * Dsz, g_qkvwT  + (size_t)d * 3 * Dsz * Dsz, Dsz, 3 * Dsz, r);
    else         tr_tile(proj_w + (size_t)d * Dsz * Dsz,     g_projwT + (size_t)d * Dsz * Dsz,     Dsz, Dsz,     r - 768);
}

__global__ void prep_weights_b(const float* __restrict__ w1, const float* __restrict__ w2) {
    int id = blockIdx.x;
    int d  = id / 2048;
    int r  = id % 2048;
    if (r < 1024) tr_tile(w1 + (size_t)d * Dsz * 4 * Dsz, g_w1T + (size_t)d * 4 * Dsz * Dsz, Dsz,     4 * Dsz, r);
    else          tr_tile(w2 + (size_t)d * 4 * Dsz * Dsz, g_w2T + (size_t)d * Dsz * 4 * Dsz, 4 * Dsz, Dsz,     r - 1024);
}

// ---------------- LayerNorm (fp32 in, fp16 out), shuffle reduction ------------------
__global__ void ln_kernel(const float* __restrict__ x, const float* __restrict__ s,
                          const float* __restrict__ b, __half* __restrict__ out) {
    int row = blockIdx.x;
    int t = threadIdx.x;
    int w = t >> 5, lane = t & 31;
    const float* xr = x + (size_t)row * Dsz;
    float v0 = xr[t], v1 = xr[t + 256];

    float a = v0 + v1, q = v0 * v0 + v1 * v1;
    #pragma unroll
    for (int m = 16; m; m >>= 1) {
        a += __shfl_xor_sync(0xffffffffu, a, m);
        q += __shfl_xor_sync(0xffffffffu, q, m);
    }
    __shared__ float pa[8], pq[8];
    if (lane == 0) { pa[w] = a; pq[w] = q; }
    __syncthreads();
    float ta = 0.f, tq = 0.f;
    #pragma unroll
    for (int i = 0; i < 8; i++) { ta += pa[i]; tq += pq[i]; }
    float mean = ta * (1.0f / Dsz);
    float var  = tq * (1.0f / Dsz) - mean * mean;
    float inv  = rsqrtf(var + 1e-5f);
    __half* orow = out + (size_t)row * Dsz;
    orow[t]       = __float2half((v0 - mean) * inv * s[t]       + b[t]);
    orow[t + 256] = __float2half((v1 - mean) * inv * s[t + 256] + b[t + 256]);
}

// ---------------- Dilated sparse attention: QT=16 queries/block, 128 threads --------
#define QT 16
template <int DIL>
__global__ void __launch_bounds__(128)
attn_kernel(const __half* __restrict__ qkv, __half* __restrict__ o) {
    constexpr int NR = QT + (Kw - 1) * DIL;
    __shared__ __half sk[NR * HDm];
    __shared__ __half sv[NR * HDm];

    const int tid = threadIdx.x;
    const int b   = blockIdx.y >> 3;
    const int h   = blockIdx.y & 7;
    const int q0  = blockIdx.x * QT;

    const int jlo   = max(0, q0 - (Kw - 1) * DIL);
    const int nrows = q0 + QT - jlo;

    const __half* kvbase = qkv + ((size_t)(b * Tsz + jlo)) * (3 * Dsz) + h * HDm;
    for (int idx = tid; idx < nrows * 8; idx += 128) {
        int row = idx >> 3, seg = idx & 7;
        const __half* src = kvbase + (size_t)row * (3 * Dsz) + seg * 8;
        *(uint4*)&sk[row * HDm + seg * 8] = *(const uint4*)(src + Dsz);
        *(uint4*)&sv[row * HDm + seg * 8] = *(const uint4*)(src + 2 * Dsz);
    }
    __syncthreads();

    const int l8 = tid & 7;
    const int q  = q0 + (tid >> 3);

    uint4 qv = *(const uint4*)(qkv + ((size_t)(b * Tsz + q)) * (3 * Dsz) + h * HDm + l8 * 8);
    float2 qf[4];
    {
        const __half2* qh = (const __half2*)&qv;
        #pragma unroll
        for (int i = 0; i < 4; i++) qf[i] = __half22float2(qh[i]);
    }

    int nv = q / DIL + 1;
    if (nv > Kw) nv = Kw;

    float sc[Kw];
    #pragma unroll
    for (int s = 0; s < Kw; s++) {
        float e = -1e30f;
        if (s < nv) {
            int r = q - s * DIL - jlo;
            uint4 kv4 = *(const uint4*)&sk[r * HDm + l8 * 8];
            const __half2* kh = (const __half2*)&kv4;
            float p = 0.f;
            #pragma unroll
            for (int i = 0; i < 4; i++) {
                float2 kf = __half22float2(kh[i]);
                p += qf[i].x * kf.x + qf[i].y * kf.y;
            }
            p += __shfl_xor_sync(0xffffffffu, p, 4);
            p += __shfl_xor_sync(0xffffffffu, p, 2);
            p += __shfl_xor_sync(0xffffffffu, p, 1);
            e = p * 0.125f;
        }
        sc[s] = e;
    }
    float mx = sc[0];
    #pragma unroll
    for (int s = 1; s < Kw; s++) mx = fmaxf(mx, sc[s]);

    float denom = 0.f;
    float oa[8] = {0.f, 0.f, 0.f, 0.f, 0.f, 0.f, 0.f, 0.f};
    #pragma unroll
    for (int s = 0; s < Kw; s++) {
        if (s < nv) {
            float wgt = __expf(sc[s] - mx);
            denom += wgt;
            int r = q - s * DIL - jlo;
            uint4 vv4 = *(const uint4*)&sv[r * HDm + l8 * 8];
            const __half2* vh = (const __half2*)&vv4;
            #pragma unroll
            for (int i = 0; i < 4; i++) {
                float2 vf = __half22float2(vh[i]);
                oa[2 * i]     += wgt * vf.x;
                oa[2 * i + 1] += wgt * vf.y;
            }
        }
    }
    float rcp = 1.0f / denom;
    __half2 oh[4];
    #pragma unroll
    for (int i = 0; i < 4; i++)
        oh[i] = __floats2half2_rn(oa[2 * i] * rcp, oa[2 * i + 1] * rcp);
    *(uint4*)(o + ((size_t)(b * Tsz + q)) * Dsz + h * HDm + l8 * 8) = *(uint4*)oh;
}

// ---------------- fp16 mma.sync GEMM, S-stage cp.async pipeline ----------------------
// C[M,N] = A[M,K] @ Bt[N,K]^T.  128 x BN_ x BK tile, 256 threads (8 warps: 4M x 2N).
// MINCTAS feeds __launch_bounds__ (3 -> regs<=85 -> 3 CTAs/SM -> 24 warps).
// EPI: 0 = store half, 1 = +bias + exact GELU -> half, 2 = +bias + residual -> float
template <int BN_, int EPI, int BK, int S, int MINCTAS>
__global__ void __launch_bounds__(256, MINCTAS)
mma_gemm(const __half* __restrict__ A, const __half* __restrict__ Bt,
         const float* __restrict__ bias, const float* __restrict__ res,
         void* __restrict__ Cv, int N, int K) {
    constexpr int BM = 128;
    constexpr int RST = BK + 8;
    constexpr int ABYTES = BM * RST * 2;
    constexpr int BBYTES = BN_ * RST * 2;
    constexpr int WN = BN_ / 2;
    constexpr int NT = WN / 8;
    constexpr int NPAIR = NT / 2;
    constexpr int AITER = (BM * BK / 8) / 256;
    constexpr int BITER = (BN_ * BK / 8) / 256;
    constexpr int KSTEPS = BK / 16;

    extern __shared__ char dsm[];
    const uint32_t sbase = smem_u32(dsm);
    const uint32_t bbase = sbase + S * ABYTES;

    const int tid  = threadIdx.x;
    const int w    = tid >> 5, lane = tid & 31;
    const int wm   = w & 3,   wn   = w >> 2;
    const int g    = lane >> 2, t4 = lane & 3;
    const int quad = lane >> 3, qr = lane & 7;
    const int bx   = blockIdx.x * BN_, by = blockIdx.y * BM;

    const __half* Ag[AITER]; uint32_t Asm[AITER];
    #pragma unroll
    for (int i = 0; i < AITER; i++) {
        int e = tid + i * 256, row = e / (BK / 8), seg = e % (BK / 8);
        Ag[i]  = A + (size_t)(by + row) * K + seg * 8;
        Asm[i] = sbase + (row * RST + seg * 8) * 2;
    }
    const __half* Bg[BITER]; uint32_t Bsm[BITER];
    #pragma unroll
    for (int i = 0; i < BITER; i++) {
        int e = tid + i * 256, row = e / (BK / 8), seg = e % (BK / 8);
        Bg[i]  = Bt + (size_t)(bx + row) * K + seg * 8;
        Bsm[i] = bbase + (row * RST + seg * 8) * 2;
    }

    uint32_t aAddr[2], bAddr[NPAIR];
    #pragma unroll
    for (int mt = 0; mt < 2; mt++) {
        int row = wm * 32 + mt * 16 + (quad & 1) * 8 + qr;
        int col = (quad >> 1) * 8;
        aAddr[mt] = sbase + (row * RST + col) * 2;
    }
    #pragma unroll
    for (int p = 0; p < NPAIR; p++) {
        int row = wn * WN + p * 16 + (quad & 1) * 8 + qr;
        int col = (quad >> 1) * 8;
        bAddr[p] = bbase + (row * RST + col) * 2;
    }

    float acc[2][NT][4];
    #pragma unroll
    for (int i = 0; i < 2; i++)
        #pragma unroll
        for (int j = 0; j < NT; j++)
            #pragma unroll
            for (int q = 0; q < 4; q++) acc[i][j][q] = 0.f;

    const int nch = K / BK;

    #pragma unroll
    for (int s = 0; s < S - 1; s++) {
        const int ko = s * BK;
        #pragma unroll
        for (int i = 0; i < AITER; i++) cp16(Asm[i] + s * ABYTES, Ag[i] + ko);
        #pragma unroll
        for (int i = 0; i < BITER; i++) cp16(Bsm[i] + s * BBYTES, Bg[i] + ko);
        asm volatile("cp.async.commit_group;");
    }

    int cst = 0;
    int lst = S - 1;

    for (int c = 0; c < nch; ++c) {
        asm volatile("cp.async.wait_group %0;" :: "n"(S - 2));
        __syncthreads();

        const int ls = c + S - 1;
        if (ls < nch) {
            const int ko = ls * BK;
            #pragma unroll
            for (int i = 0; i < AITER; i++) cp16(Asm[i] + lst * ABYTES, Ag[i] + ko);
            #pragma unroll
            for (int i = 0; i < BITER; i++) cp16(Bsm[i] + lst * BBYTES, Bg[i] + ko);
        }
        asm volatile("cp.async.commit_group;");

        const uint32_t aOff = cst * ABYTES;
        const uint32_t bOff = cst * BBYTES;
        #pragma unroll
        for (int ks = 0; ks < KSTEPS; ks++) {
            const uint32_t kb = ks * 32;
            uint32_t af[2][4];
            #pragma unroll
            for (int mt = 0; mt < 2; mt++) ldsm4(af[mt], aAddr[mt] + aOff + kb);
            uint32_t bf[NPAIR][4];
            #pragma unroll
            for (int p = 0; p < NPAIR; p++) ldsm4(bf[p], bAddr[p] + bOff + kb);
            #pragma unroll
            for (int mt = 0; mt < 2; mt++)
                #pragma unroll
                for (int p = 0; p < NPAIR; p++) {
                    uint32_t b0[2] = { bf[p][0], bf[p][2] };
                    uint32_t b1[2] = { bf[p][1], bf[p][3] };
                    mma_f16(acc[mt][2 * p],     af[mt], b0);
                    mma_f16(acc[mt][2 * p + 1], af[mt], b1);
                }
        }
        cst = (cst == S - 1) ? 0 : cst + 1;
        lst = (lst == S - 1) ? 0 : lst + 1;
    }

    #pragma unroll
    for (int mt = 0; mt < 2; mt++) {
        const int r0 = by + wm * 32 + mt * 16 + g;
        #pragma unroll
        for (int nt = 0; nt < NT; nt++) {
            const int col = bx + wn * WN + nt * 8 + 2 * t4;
            float v0 = acc[mt][nt][0], v1 = acc[mt][nt][1];
            float v2 = acc[mt][nt][2], v3 = acc[mt][nt][3];
            if (EPI != 0) {
                float2 bb = *(const float2*)&bias[col];
                v0 += bb.x; v1 += bb.y; v2 += bb.x; v3 += bb.y;
            }
            if (EPI == 1) {
                v0 = 0.5f * v0 * (1.0f + erff(v0 * 0.70710678118654752f));
                v1 = 0.5f * v1 * (1.0f + erff(v1 * 0.70710678118654752f));
                v2 = 0.5f * v2 * (1.0f + erff(v2 * 0.70710678118654752f));
                v3 = 0.5f * v3 * (1.0f + erff(v3 * 0.70710678118654752f));
            }
            if (EPI == 2) {
                float* C = (float*)Cv;
                float2 ra = *(const float2*)&res[(size_t)r0 * N + col];
                float2 rb = *(const float2*)&res[(size_t)(r0 + 8) * N + col];
                float2 o01 = { v0 + ra.x, v1 + ra.y };
                float2 o23 = { v2 + rb.x, v3 + rb.y };
                *(float2*)&C[(size_t)r0 * N + col]       = o01;
                *(float2*)&C[(size_t)(r0 + 8) * N + col] = o23;
            } else {
                __half* C = (__half*)Cv;
                *(__half2*)&C[(size_t)r0 * N + col]       = __floats2half2_rn(v0, v1);
                *(__half2*)&C[(size_t)(r0 + 8) * N + col] = __floats2half2_rn(v2, v3);
            }
        }
    }
}

// ---------------- launcher -----------------------------------------------------------
// ALL GEMMs: BN=64, BK=32, S=4, 3 CTAs/SM -> 61440 bytes smem, regs forced <= 85
#define SMEM64   61440

extern "C" void kernel_launch(void* const* d_in, const int* in_sizes, int n_in,
                              void* d_out, int out_size) {
    const float* x_in   = (const float*)d_in[0];
    const float* ln1_s  = (const float*)d_in[1];
    const float* ln1_b  = (const float*)d_in[2];
    const float* qkv_w  = (const float*)d_in[3];
    const float* proj_w = (const float*)d_in[4];
    const float* proj_b = (const float*)d_in[5];
    const float* ln2_s  = (const float*)d_in[6];
    const float* ln2_b  = (const float*)d_in[7];
    const float* w1     = (const float*)d_in[8];
    const float* b1     = (const float*)d_in[9];
    const float* w2     = (const float*)d_in[10];
    const float* b2     = (const float*)d_in[11];

    float* x = (float*)d_out;

    __half *h, *qkv, *o, *mlp, *qkvT, *projT, *w1T, *w2T;
    cudaGetSymbolAddress((void**)&h,     g_h);
    cudaGetSymbolAddress((void**)&qkv,   g_qkv);
    cudaGetSymbolAddress((void**)&o,     g_o);
    cudaGetSymbolAddress((void**)&mlp,   g_mlp);
    cudaGetSymbolAddress((void**)&qkvT,  g_qkvwT);
    cudaGetSymbolAddress((void**)&projT, g_projwT);
    cudaGetSymbolAddress((void**)&w1T,   g_w1T);
    cudaGetSymbolAddress((void**)&w2T,   g_w2T);

    cudaFuncSetAttribute((const void*)mma_gemm<64,0,32,4,3>, cudaFuncAttributeMaxDynamicSharedMemorySize, SMEM64);
    cudaFuncSetAttribute((const void*)mma_gemm<64,1,32,4,3>, cudaFuncAttributeMaxDynamicSharedMemorySize, SMEM64);
    cudaFuncSetAttribute((const void*)mma_gemm<64,2,32,4,3>, cudaFuncAttributeMaxDynamicSharedMemorySize, SMEM64);

    // launches #1,#2: weight prep (keeps the qkv GEMM at launch #4 for profiling)
    prep_weights_a<<<NDEPTH * 1024, dim3(32, 8)>>>(qkv_w, proj_w);
    prep_weights_b<<<NDEPTH * 2048, dim3(32, 8)>>>(w1, w2);

    for (int d = 0; d < NDEPTH; d++) {
        const float* xr = (d == 0) ? x_in : x;

        ln_kernel<<<ROWS, 256>>>(xr, ln1_s + d * Dsz, ln1_b + d * Dsz, h);

        // qkv = h @ qkv_w   (4096 x 1536 x 512)
        mma_gemm<64,0,32,4,3><<<dim3((3 * Dsz) / 64, ROWS / 128), 256, SMEM64>>>(
            h, qkvT + (size_t)d * 3 * Dsz * Dsz, nullptr, nullptr, qkv, 3 * Dsz, Dsz);

        // sparse dilated attention
        dim3 agrid(Tsz / QT, Bsz * Hn);
        if (d == 0)      attn_kernel<1><<<agrid, 128>>>(qkv, o);
        else if (d == 1) attn_kernel<2><<<agrid, 128>>>(qkv, o);
        else             attn_kernel<4><<<agrid, 128>>>(qkv, o);

        // x = xr + o @ proj_w + proj_b   (4096 x 512 x 512)
        mma_gemm<64,2,32,4,3><<<dim3(Dsz / 64, ROWS / 128), 256, SMEM64>>>(
            o, projT + (size_t)d * Dsz * Dsz, proj_b + d * Dsz, xr, x, Dsz, Dsz);

        ln_kernel<<<ROWS, 256>>>(x, ln2_s + d * Dsz, ln2_b + d * Dsz, h);

        // mlp = gelu(h @ w1 + b1)   (4096 x 2048 x 512)
        mma_gemm<64,1,32,4,3><<<dim3((4 * Dsz) / 64, ROWS / 128), 256, SMEM64>>>(
            h, w1T + (size_t)d * Dsz * 4 * Dsz, b1 + (size_t)d * 4 * Dsz, nullptr,
            mlp, 4 * Dsz, Dsz);

        // x = x + mlp @ w2 + b2   (4096 x 512 x 2048)
        mma_gemm<64,2,32,4,3><<<dim3(Dsz / 64, ROWS / 128), 256, SMEM64>>>(
            mlp, w2T + (size_t)d * Dsz * 4 * Dsz, b2 + d * Dsz, x, x, Dsz, 4 * Dsz);
    }
}

// round 13
// speedup vs baseline: 1.0396x; 1.0396x over previous
#include <cuda_runtime.h>
#include <cuda_fp16.h>
#include <math.h>
#include <stdint.h>

#define Bsz   2
#define Tsz   2048
#define Dsz   512
#define Hn    8
#define HDm   64
#define Kw    16
#define NDEPTH 3
#define ROWS  (Bsz*Tsz)   // 4096

// ---------------- scratch (static device globals; no allocation) ----------------
__device__ __half g_h[ROWS * Dsz];
__device__ __half g_qkv[ROWS * 3 * Dsz];
__device__ __half g_o[ROWS * Dsz];
__device__ __half g_mlp[ROWS * 4 * Dsz];
// transposed fp16 weights ([N,K], K contiguous)
__device__ __half g_qkvwT[NDEPTH * 3 * Dsz * Dsz];
__device__ __half g_projwT[NDEPTH * Dsz * Dsz];
__device__ __half g_w1T[NDEPTH * 4 * Dsz * Dsz];
__device__ __half g_w2T[NDEPTH * Dsz * 4 * Dsz];

// ---------------- helpers ----------------------------------------------------------
__device__ __forceinline__ uint32_t smem_u32(const void* p) {
    uint32_t a;
    asm("{ .reg .u64 t; cvta.to.shared.u64 t, %1; cvt.u32.u64 %0, t; }" : "=r"(a) : "l"(p));
    return a;
}
__device__ __forceinline__ void cp16(uint32_t s, const void* g) {
    asm volatile("cp.async.cg.shared.global [%0], [%1], 16;" :: "r"(s), "l"(g));
}
__device__ __forceinline__ void ldsm4(uint32_t* r, uint32_t addr) {
    asm volatile("ldmatrix.sync.aligned.m8n8.x4.shared.b16 {%0,%1,%2,%3}, [%4];"
                 : "=r"(r[0]), "=r"(r[1]), "=r"(r[2]), "=r"(r[3]) : "r"(addr));
}
__device__ __forceinline__ void mma_f16(float* c, const uint32_t* a, const uint32_t* b) {
    asm volatile(
        "mma.sync.aligned.m16n8k16.row.col.f32.f16.f16.f32 "
        "{%0,%1,%2,%3}, {%4,%5,%6,%7}, {%8,%9}, {%0,%1,%2,%3};"
        : "+f"(c[0]), "+f"(c[1]), "+f"(c[2]), "+f"(c[3])
        : "r"(a[0]), "r"(a[1]), "r"(a[2]), "r"(a[3]), "r"(b[0]), "r"(b[1]));
}

// ---------------- weight prep (split in two launches for profiling order) -----------
__device__ __forceinline__ void tr_tile(const float* in, __half* out, int R, int C, int t0) {
    __shared__ float tile[32][33];
    int tpc = C / 32;
    int r0 = (t0 / tpc) * 32, c0 = (t0 % tpc) * 32;
    int tx = threadIdx.x, ty = threadIdx.y;   // (32, 8)
    #pragma unroll
    for (int i = 0; i < 32; i += 8)
        tile[ty + i][tx] = in[(size_t)(r0 + ty + i) * C + c0 + tx];
    __syncthreads();
    #pragma unroll
    for (int i = 0; i < 32; i += 8)
        out[(size_t)(c0 + ty + i) * R + r0 + tx] = __float2half(tile[tx][ty + i]);
}

__global__ void prep_weights_a(const float* __restrict__ qkv_w, const float* __restrict__ proj_w) {
    int id = blockIdx.x;
    int d  = id / 1024;
    int r  = id % 1024;
    if (r < 768) tr_tile(qkv_w  + (size_t)d * Dsz * 3 * Dsz, g_qkvwT  + (size_t)d * 3 * Dsz * Dsz, Dsz, 3 * Dsz, r);
    else         tr_tile(proj_w + (size_t)d * Dsz * Dsz,     g_projwT + (size_t)d * Dsz * Dsz,     Dsz, Dsz,     r - 768);
}

__global__ void prep_weights_b(const float* __restrict__ w1, const float* __restrict__ w2) {
    int id = blockIdx.x;
    int d  = id / 2048;
    int r  = id % 2048;
    if (r < 1024) tr_tile(w1 + (size_t)d * Dsz * 4 * Dsz, g_w1T + (size_t)d * 4 * Dsz * Dsz, Dsz,     4 * Dsz, r);
    else          tr_tile(w2 + (size_t)d * 4 * Dsz * Dsz, g_w2T + (size_t)d * Dsz * 4 * Dsz, 4 * Dsz, Dsz,     r - 1024);
}

// ---------------- LayerNorm (fp32 in, fp16 out), shuffle reduction ------------------
__global__ void ln_kernel(const float* __restrict__ x, const float* __restrict__ s,
                          const float* __restrict__ b, __half* __restrict__ out) {
    int row = blockIdx.x;
    int t = threadIdx.x;
    int w = t >> 5, lane = t & 31;
    const float* xr = x + (size_t)row * Dsz;
    float v0 = xr[t], v1 = xr[t + 256];

    float a = v0 + v1, q = v0 * v0 + v1 * v1;
    #pragma unroll
    for (int m = 16; m; m >>= 1) {
        a += __shfl_xor_sync(0xffffffffu, a, m);
        q += __shfl_xor_sync(0xffffffffu, q, m);
    }
    __shared__ float pa[8], pq[8];
    if (lane == 0) { pa[w] = a; pq[w] = q; }
    __syncthreads();
    float ta = 0.f, tq = 0.f;
    #pragma unroll
    for (int i = 0; i < 8; i++) { ta += pa[i]; tq += pq[i]; }
    float mean = ta * (1.0f / Dsz);
    float var  = tq * (1.0f / Dsz) - mean * mean;
    float inv  = rsqrtf(var + 1e-5f);
    __half* orow = out + (size_t)row * Dsz;
    orow[t]       = __float2half((v0 - mean) * inv * s[t]       + b[t]);
    orow[t + 256] = __float2half((v1 - mean) * inv * s[t + 256] + b[t + 256]);
}

// ---------------- Dilated sparse attention: QT=16 queries/block, 128 threads --------
#define QT 16
template <int DIL>
__global__ void __launch_bounds__(128)
attn_kernel(const __half* __restrict__ qkv, __half* __restrict__ o) {
    constexpr int NR = QT + (Kw - 1) * DIL;
    __shared__ __half sk[NR * HDm];
    __shared__ __half sv[NR * HDm];

    const int tid = threadIdx.x;
    const int b   = blockIdx.y >> 3;
    const int h   = blockIdx.y & 7;
    const int q0  = blockIdx.x * QT;

    const int jlo   = max(0, q0 - (Kw - 1) * DIL);
    const int nrows = q0 + QT - jlo;

    const __half* kvbase = qkv + ((size_t)(b * Tsz + jlo)) * (3 * Dsz) + h * HDm;
    for (int idx = tid; idx < nrows * 8; idx += 128) {
        int row = idx >> 3, seg = idx & 7;
        const __half* src = kvbase + (size_t)row * (3 * Dsz) + seg * 8;
        *(uint4*)&sk[row * HDm + seg * 8] = *(const uint4*)(src + Dsz);
        *(uint4*)&sv[row * HDm + seg * 8] = *(const uint4*)(src + 2 * Dsz);
    }
    __syncthreads();

    const int l8 = tid & 7;
    const int q  = q0 + (tid >> 3);

    uint4 qv = *(const uint4*)(qkv + ((size_t)(b * Tsz + q)) * (3 * Dsz) + h * HDm + l8 * 8);
    float2 qf[4];
    {
        const __half2* qh = (const __half2*)&qv;
        #pragma unroll
        for (int i = 0; i < 4; i++) qf[i] = __half22float2(qh[i]);
    }

    int nv = q / DIL + 1;
    if (nv > Kw) nv = Kw;

    float sc[Kw];
    #pragma unroll
    for (int s = 0; s < Kw; s++) {
        float e = -1e30f;
        if (s < nv) {
            int r = q - s * DIL - jlo;
            uint4 kv4 = *(const uint4*)&sk[r * HDm + l8 * 8];
            const __half2* kh = (const __half2*)&kv4;
            float p = 0.f;
            #pragma unroll
            for (int i = 0; i < 4; i++) {
                float2 kf = __half22float2(kh[i]);
                p += qf[i].x * kf.x + qf[i].y * kf.y;
            }
            p += __shfl_xor_sync(0xffffffffu, p, 4);
            p += __shfl_xor_sync(0xffffffffu, p, 2);
            p += __shfl_xor_sync(0xffffffffu, p, 1);
            e = p * 0.125f;
        }
        sc[s] = e;
    }
    float mx = sc[0];
    #pragma unroll
    for (int s = 1; s < Kw; s++) mx = fmaxf(mx, sc[s]);

    float denom = 0.f;
    float oa[8] = {0.f, 0.f, 0.f, 0.f, 0.f, 0.f, 0.f, 0.f};
    #pragma unroll
    for (int s = 0; s < Kw; s++) {
        if (s < nv) {
            float wgt = __expf(sc[s] - mx);
            denom += wgt;
            int r = q - s * DIL - jlo;
            uint4 vv4 = *(const uint4*)&sv[r * HDm + l8 * 8];
            const __half2* vh = (const __half2*)&vv4;
            #pragma unroll
            for (int i = 0; i < 4; i++) {
                float2 vf = __half22float2(vh[i]);
                oa[2 * i]     += wgt * vf.x;
                oa[2 * i + 1] += wgt * vf.y;
            }
        }
    }
    float rcp = 1.0f / denom;
    __half2 oh[4];
    #pragma unroll
    for (int i = 0; i < 4; i++)
        oh[i] = __floats2half2_rn(oa[2 * i] * rcp, oa[2 * i + 1] * rcp);
    *(uint4*)(o + ((size_t)(b * Tsz + q)) * Dsz + h * HDm + l8 * 8) = *(uint4*)oh;
}

// ---------------- fp16 mma.sync GEMM, S-stage cp.async pipeline ----------------------
// C[M,N] = A[M,K] @ Bt[N,K]^T.  128 x BN_ x BK tile, 256 threads (8 warps: 4M x 2N).
// EPI: 0 = store half, 1 = +bias + exact GELU -> half, 2 = +bias + residual -> float
template <int BN_, int EPI, int BK, int S, int MINCTAS>
__global__ void __launch_bounds__(256, MINCTAS)
mma_gemm(const __half* __restrict__ A, const __half* __restrict__ Bt,
         const float* __restrict__ bias, const float* __restrict__ res,
         void* __restrict__ Cv, int N, int K) {
    constexpr int BM = 128;
    constexpr int RST = BK + 8;
    constexpr int ABYTES = BM * RST * 2;
    constexpr int BBYTES = BN_ * RST * 2;
    constexpr int WN = BN_ / 2;
    constexpr int NT = WN / 8;
    constexpr int NPAIR = NT / 2;
    constexpr int AITER = (BM * BK / 8) / 256;
    constexpr int BITER = (BN_ * BK / 8) / 256;
    constexpr int KSTEPS = BK / 16;

    extern __shared__ char dsm[];
    const uint32_t sbase = smem_u32(dsm);
    const uint32_t bbase = sbase + S * ABYTES;

    const int tid  = threadIdx.x;
    const int w    = tid >> 5, lane = tid & 31;
    const int wm   = w & 3,   wn   = w >> 2;
    const int g    = lane >> 2, t4 = lane & 3;
    const int quad = lane >> 3, qr = lane & 7;
    const int bx   = blockIdx.x * BN_, by = blockIdx.y * BM;

    const __half* Ag[AITER]; uint32_t Asm[AITER];
    #pragma unroll
    for (int i = 0; i < AITER; i++) {
        int e = tid + i * 256, row = e / (BK / 8), seg = e % (BK / 8);
        Ag[i]  = A + (size_t)(by + row) * K + seg * 8;
        Asm[i] = sbase + (row * RST + seg * 8) * 2;
    }
    const __half* Bg[BITER]; uint32_t Bsm[BITER];
    #pragma unroll
    for (int i = 0; i < BITER; i++) {
        int e = tid + i * 256, row = e / (BK / 8), seg = e % (BK / 8);
        Bg[i]  = Bt + (size_t)(bx + row) * K + seg * 8;
        Bsm[i] = bbase + (row * RST + seg * 8) * 2;
    }

    uint32_t aAddr[2], bAddr[NPAIR];
    #pragma unroll
    for (int mt = 0; mt < 2; mt++) {
        int row = wm * 32 + mt * 16 + (quad & 1) * 8 + qr;
        int col = (quad >> 1) * 8;
        aAddr[mt] = sbase + (row * RST + col) * 2;
    }
    #pragma unroll
    for (int p = 0; p < NPAIR; p++) {
        int row = wn * WN + p * 16 + (quad & 1) * 8 + qr;
        int col = (quad >> 1) * 8;
        bAddr[p] = bbase + (row * RST + col) * 2;
    }

    float acc[2][NT][4];
    #pragma unroll
    for (int i = 0; i < 2; i++)
        #pragma unroll
        for (int j = 0; j < NT; j++)
            #pragma unroll
            for (int q = 0; q < 4; q++) acc[i][j][q] = 0.f;

    const int nch = K / BK;

    #pragma unroll
    for (int s = 0; s < S - 1; s++) {
        const int ko = s * BK;
        #pragma unroll
        for (int i = 0; i < AITER; i++) cp16(Asm[i] + s * ABYTES, Ag[i] + ko);
        #pragma unroll
        for (int i = 0; i < BITER; i++) cp16(Bsm[i] + s * BBYTES, Bg[i] + ko);
        asm volatile("cp.async.commit_group;");
    }

    int cst = 0;
    int lst = S - 1;

    for (int c = 0; c < nch; ++c) {
        asm volatile("cp.async.wait_group %0;" :: "n"(S - 2));
        __syncthreads();

        const int ls = c + S - 1;
        if (ls < nch) {
            const int ko = ls * BK;
            #pragma unroll
            for (int i = 0; i < AITER; i++) cp16(Asm[i] + lst * ABYTES, Ag[i] + ko);
            #pragma unroll
            for (int i = 0; i < BITER; i++) cp16(Bsm[i] + lst * BBYTES, Bg[i] + ko);
        }
        asm volatile("cp.async.commit_group;");

        const uint32_t aOff = cst * ABYTES;
        const uint32_t bOff = cst * BBYTES;
        #pragma unroll
        for (int ks = 0; ks < KSTEPS; ks++) {
            const uint32_t kb = ks * 32;
            uint32_t af[2][4];
            #pragma unroll
            for (int mt = 0; mt < 2; mt++) ldsm4(af[mt], aAddr[mt] + aOff + kb);
            uint32_t bf[NPAIR][4];
            #pragma unroll
            for (int p = 0; p < NPAIR; p++) ldsm4(bf[p], bAddr[p] + bOff + kb);
            #pragma unroll
            for (int mt = 0; mt < 2; mt++)
                #pragma unroll
                for (int p = 0; p < NPAIR; p++) {
                    uint32_t b0[2] = { bf[p][0], bf[p][2] };
                    uint32_t b1[2] = { bf[p][1], bf[p][3] };
                    mma_f16(acc[mt][2 * p],     af[mt], b0);
                    mma_f16(acc[mt][2 * p + 1], af[mt], b1);
                }
        }
        cst = (cst == S - 1) ? 0 : cst + 1;
        lst = (lst == S - 1) ? 0 : lst + 1;
    }

    #pragma unroll
    for (int mt = 0; mt < 2; mt++) {
        const int r0 = by + wm * 32 + mt * 16 + g;
        #pragma unroll
        for (int nt = 0; nt < NT; nt++) {
            const int col = bx + wn * WN + nt * 8 + 2 * t4;
            float v0 = acc[mt][nt][0], v1 = acc[mt][nt][1];
            float v2 = acc[mt][nt][2], v3 = acc[mt][nt][3];
            if (EPI != 0) {
                float2 bb = *(const float2*)&bias[col];
                v0 += bb.x; v1 += bb.y; v2 += bb.x; v3 += bb.y;
            }
            if (EPI == 1) {
                v0 = 0.5f * v0 * (1.0f + erff(v0 * 0.70710678118654752f));
                v1 = 0.5f * v1 * (1.0f + erff(v1 * 0.70710678118654752f));
                v2 = 0.5f * v2 * (1.0f + erff(v2 * 0.70710678118654752f));
                v3 = 0.5f * v3 * (1.0f + erff(v3 * 0.70710678118654752f));
            }
            if (EPI == 2) {
                float* C = (float*)Cv;
                float2 ra = *(const float2*)&res[(size_t)r0 * N + col];
                float2 rb = *(const float2*)&res[(size_t)(r0 + 8) * N + col];
                float2 o01 = { v0 + ra.x, v1 + ra.y };
                float2 o23 = { v2 + rb.x, v3 + rb.y };
                *(float2*)&C[(size_t)r0 * N + col]       = o01;
                *(float2*)&C[(size_t)(r0 + 8) * N + col] = o23;
            } else {
                __half* C = (__half*)Cv;
                *(__half2*)&C[(size_t)r0 * N + col]       = __floats2half2_rn(v0, v1);
                *(__half2*)&C[(size_t)(r0 + 8) * N + col] = __floats2half2_rn(v2, v3);
            }
        }
    }
}

// ---------------- launcher -----------------------------------------------------------
// BN=128: BK=64, S=3, 2 CTAs/SM -> 110592 bytes  [qkv, mlp1]
// BN=64 : BK=32, S=4, 3 CTAs/SM -> 61440  bytes  [proj, mlp2]
#define SMEM128  110592
#define SMEM64   61440

extern "C" void kernel_launch(void* const* d_in, const int* in_sizes, int n_in,
                              void* d_out, int out_size) {
    const float* x_in   = (const float*)d_in[0];
    const float* ln1_s  = (const float*)d_in[1];
    const float* ln1_b  = (const float*)d_in[2];
    const float* qkv_w  = (const float*)d_in[3];
    const float* proj_w = (const float*)d_in[4];
    const float* proj_b = (const float*)d_in[5];
    const float* ln2_s  = (const float*)d_in[6];
    const float* ln2_b  = (const float*)d_in[7];
    const float* w1     = (const float*)d_in[8];
    const float* b1     = (const float*)d_in[9];
    const float* w2     = (const float*)d_in[10];
    const float* b2     = (const float*)d_in[11];

    float* x = (float*)d_out;

    __half *h, *qkv, *o, *mlp, *qkvT, *projT, *w1T, *w2T;
    cudaGetSymbolAddress((void**)&h,     g_h);
    cudaGetSymbolAddress((void**)&qkv,   g_qkv);
    cudaGetSymbolAddress((void**)&o,     g_o);
    cudaGetSymbolAddress((void**)&mlp,   g_mlp);
    cudaGetSymbolAddress((void**)&qkvT,  g_qkvwT);
    cudaGetSymbolAddress((void**)&projT, g_projwT);
    cudaGetSymbolAddress((void**)&w1T,   g_w1T);
    cudaGetSymbolAddress((void**)&w2T,   g_w2T);

    cudaFuncSetAttribute((const void*)mma_gemm<128,0,64,3,2>, cudaFuncAttributeMaxDynamicSharedMemorySize, SMEM128);
    cudaFuncSetAttribute((const void*)mma_gemm<128,1,64,3,2>, cudaFuncAttributeMaxDynamicSharedMemorySize, SMEM128);
    cudaFuncSetAttribute((const void*)mma_gemm<64,2,32,4,3>,  cudaFuncAttributeMaxDynamicSharedMemorySize, SMEM64);

    // launches #1,#2: weight prep (keeps the qkv GEMM at launch #4 for profiling)
    prep_weights_a<<<NDEPTH * 1024, dim3(32, 8)>>>(qkv_w, proj_w);
    prep_weights_b<<<NDEPTH * 2048, dim3(32, 8)>>>(w1, w2);

    for (int d = 0; d < NDEPTH; d++) {
        const float* xr = (d == 0) ? x_in : x;

        ln_kernel<<<ROWS, 256>>>(xr, ln1_s + d * Dsz, ln1_b + d * Dsz, h);

        // qkv = h @ qkv_w   (4096 x 1536 x 512)
        mma_gemm<128,0,64,3,2><<<dim3((3 * Dsz) / 128, ROWS / 128), 256, SMEM128>>>(
            h, qkvT + (size_t)d * 3 * Dsz * Dsz, nullptr, nullptr, qkv, 3 * Dsz, Dsz);

        // sparse dilated attention
        dim3 agrid(Tsz / QT, Bsz * Hn);
        if (d == 0)      attn_kernel<1><<<agrid, 128>>>(qkv, o);
        else if (d == 1) attn_kernel<2><<<agrid, 128>>>(qkv, o);
        else             attn_kernel<4><<<agrid, 128>>>(qkv, o);

        // x = xr + o @ proj_w + proj_b   (4096 x 512 x 512)
        mma_gemm<64,2,32,4,3><<<dim3(Dsz / 64, ROWS / 128), 256, SMEM64>>>(
            o, projT + (size_t)d * Dsz * Dsz, proj_b + d * Dsz, xr, x, Dsz, Dsz);

        ln_kernel<<<ROWS, 256>>>(x, ln2_s + d * Dsz, ln2_b + d * Dsz, h);

        // mlp = gelu(h @ w1 + b1)   (4096 x 2048 x 512)
        mma_gemm<128,1,64,3,2><<<dim3((4 * Dsz) / 128, ROWS / 128), 256, SMEM128>>>(
            h, w1T + (size_t)d * Dsz * 4 * Dsz, b1 + (size_t)d * 4 * Dsz, nullptr,
            mlp, 4 * Dsz, Dsz);

        // x = x + mlp @ w2 + b2   (4096 x 512 x 2048)
        mma_gemm<64,2,32,4,3><<<dim3(Dsz / 64, ROWS / 128), 256, SMEM64>>>(
            mlp, w2T + (size_t)d * Dsz * 4 * Dsz, b2 + d * Dsz, x, x, Dsz, 4 * Dsz);
    }
}

// round 14
// speedup vs baseline: 1.0519x; 1.0118x over previous
#include <cuda_runtime.h>
#include <cuda_fp16.h>
#include <math.h>
#include <stdint.h>

#define Bsz   2
#define Tsz   2048
#define Dsz   512
#define Hn    8
#define HDm   64
#define Kw    16
#define NDEPTH 3
#define ROWS  (Bsz*Tsz)   // 4096

// ---------------- scratch (static device globals; no allocation) ----------------
__device__ __half g_h[ROWS * Dsz];
__device__ __half g_qkv[ROWS * 3 * Dsz];
__device__ __half g_o[ROWS * Dsz];
__device__ __half g_mlp[ROWS * 4 * Dsz];
// transposed fp16 weights ([N,K], K contiguous)
__device__ __half g_qkvwT[NDEPTH * 3 * Dsz * Dsz];
__device__ __half g_projwT[NDEPTH * Dsz * Dsz];
__device__ __half g_w1T[NDEPTH * 4 * Dsz * Dsz];
__device__ __half g_w2T[NDEPTH * Dsz * 4 * Dsz];

// ---------------- helpers ----------------------------------------------------------
__device__ __forceinline__ uint32_t smem_u32(const void* p) {
    uint32_t a;
    asm("{ .reg .u64 t; cvta.to.shared.u64 t, %1; cvt.u32.u64 %0, t; }" : "=r"(a) : "l"(p));
    return a;
}
__device__ __forceinline__ void cp16(uint32_t s, const void* g) {
    asm volatile("cp.async.cg.shared.global [%0], [%1], 16;" :: "r"(s), "l"(g));
}
__device__ __forceinline__ void ldsm4(uint32_t* r, uint32_t addr) {
    asm volatile("ldmatrix.sync.aligned.m8n8.x4.shared.b16 {%0,%1,%2,%3}, [%4];"
                 : "=r"(r[0]), "=r"(r[1]), "=r"(r[2]), "=r"(r[3]) : "r"(addr));
}
__device__ __forceinline__ void mma_f16(float* c, const uint32_t* a, const uint32_t* b) {
    asm volatile(
        "mma.sync.aligned.m16n8k16.row.col.f32.f16.f16.f32 "
        "{%0,%1,%2,%3}, {%4,%5,%6,%7}, {%8,%9}, {%0,%1,%2,%3};"
        : "+f"(c[0]), "+f"(c[1]), "+f"(c[2]), "+f"(c[3])
        : "r"(a[0]), "r"(a[1]), "r"(a[2]), "r"(a[3]), "r"(b[0]), "r"(b[1]));
}

// ---------------- weight prep (split in two launches for profiling order) -----------
__device__ __forceinline__ void tr_tile(const float* in, __half* out, int R, int C, int t0) {
    __shared__ float tile[32][33];
    int tpc = C / 32;
    int r0 = (t0 / tpc) * 32, c0 = (t0 % tpc) * 32;
    int tx = threadIdx.x, ty = threadIdx.y;   // (32, 8)
    #pragma unroll
    for (int i = 0; i < 32; i += 8)
        tile[ty + i][tx] = in[(size_t)(r0 + ty + i) * C + c0 + tx];
    __syncthreads();
    #pragma unroll
    for (int i = 0; i < 32; i += 8)
        out[(size_t)(c0 + ty + i) * R + r0 + tx] = __float2half(tile[tx][ty + i]);
}

__global__ void prep_weights_a(const float* __restrict__ qkv_w, const float* __restrict__ proj_w) {
    int id = blockIdx.x;
    int d  = id / 1024;
    int r  = id % 1024;
    if (r < 768) tr_tile(qkv_w  + (size_t)d * Dsz * 3 * Dsz, g_qkvwT  + (size_t)d * 3 * Dsz * Dsz, Dsz, 3 * Dsz, r);
    else         tr_tile(proj_w + (size_t)d * Dsz * Dsz,     g_projwT + (size_t)d * Dsz * Dsz,     Dsz, Dsz,     r - 768);
}

__global__ void prep_weights_b(const float* __restrict__ w1, const float* __restrict__ w2) {
    int id = blockIdx.x;
    int d  = id / 2048;
    int r  = id % 2048;
    if (r < 1024) tr_tile(w1 + (size_t)d * Dsz * 4 * Dsz, g_w1T + (size_t)d * 4 * Dsz * Dsz, Dsz,     4 * Dsz, r);
    else          tr_tile(w2 + (size_t)d * 4 * Dsz * Dsz, g_w2T + (size_t)d * Dsz * 4 * Dsz, 4 * Dsz, Dsz,     r - 1024);
}

// ---------------- LayerNorm (fp32 in, fp16 out), shuffle reduction ------------------
__global__ void ln_kernel(const float* __restrict__ x, const float* __restrict__ s,
                          const float* __restrict__ b, __half* __restrict__ out) {
    int row = blockIdx.x;
    int t = threadIdx.x;
    int w = t >> 5, lane = t & 31;
    const float* xr = x + (size_t)row * Dsz;
    float v0 = xr[t], v1 = xr[t + 256];

    float a = v0 + v1, q = v0 * v0 + v1 * v1;
    #pragma unroll
    for (int m = 16; m; m >>= 1) {
        a += __shfl_xor_sync(0xffffffffu, a, m);
        q += __shfl_xor_sync(0xffffffffu, q, m);
    }
    __shared__ float pa[8], pq[8];
    if (lane == 0) { pa[w] = a; pq[w] = q; }
    __syncthreads();
    float ta = 0.f, tq = 0.f;
    #pragma unroll
    for (int i = 0; i < 8; i++) { ta += pa[i]; tq += pq[i]; }
    float mean = ta * (1.0f / Dsz);
    float var  = tq * (1.0f / Dsz) - mean * mean;
    float inv  = rsqrtf(var + 1e-5f);
    __half* orow = out + (size_t)row * Dsz;
    orow[t]       = __float2half((v0 - mean) * inv * s[t]       + b[t]);
    orow[t + 256] = __float2half((v1 - mean) * inv * s[t + 256] + b[t + 256]);
}

// ---------------- Dilated sparse attention: QT=16 queries/block, 128 threads --------
// fp16x2 inner math: score dot via __hfma2 (fp32 cross-lane reduce), V accumulation
// in half2 accumulators. Softmax weights computed in fp32.
#define QT 16
template <int DIL>
__global__ void __launch_bounds__(128)
attn_kernel(const __half* __restrict__ qkv, __half* __restrict__ o) {
    constexpr int NR = QT + (Kw - 1) * DIL;
    __shared__ __half sk[NR * HDm];
    __shared__ __half sv[NR * HDm];

    const int tid = threadIdx.x;
    const int b   = blockIdx.y >> 3;
    const int h   = blockIdx.y & 7;
    const int q0  = blockIdx.x * QT;

    const int jlo   = max(0, q0 - (Kw - 1) * DIL);
    const int nrows = q0 + QT - jlo;

    const __half* kvbase = qkv + ((size_t)(b * Tsz + jlo)) * (3 * Dsz) + h * HDm;
    for (int idx = tid; idx < nrows * 8; idx += 128) {
        int row = idx >> 3, seg = idx & 7;
        const __half* src = kvbase + (size_t)row * (3 * Dsz) + seg * 8;
        *(uint4*)&sk[row * HDm + seg * 8] = *(const uint4*)(src + Dsz);
        *(uint4*)&sv[row * HDm + seg * 8] = *(const uint4*)(src + 2 * Dsz);
    }
    __syncthreads();

    const int l8 = tid & 7;
    const int q  = q0 + (tid >> 3);

    uint4 qv = *(const uint4*)(qkv + ((size_t)(b * Tsz + q)) * (3 * Dsz) + h * HDm + l8 * 8);
    const __half2* qh = (const __half2*)&qv;

    int nv = q / DIL + 1;
    if (nv > Kw) nv = Kw;

    float sc[Kw];
    #pragma unroll
    for (int s = 0; s < Kw; s++) {
        float e = -1e30f;
        if (s < nv) {
            int r = q - s * DIL - jlo;
            uint4 kv4 = *(const uint4*)&sk[r * HDm + l8 * 8];
            const __half2* kh = (const __half2*)&kv4;
            __half2 ph = __hmul2(qh[0], kh[0]);
            ph = __hfma2(qh[1], kh[1], ph);
            ph = __hfma2(qh[2], kh[2], ph);
            ph = __hfma2(qh[3], kh[3], ph);
            float p = __half2float(__low2half(ph)) + __half2float(__high2half(ph));
            p += __shfl_xor_sync(0xffffffffu, p, 4);
            p += __shfl_xor_sync(0xffffffffu, p, 2);
            p += __shfl_xor_sync(0xffffffffu, p, 1);
            e = p * 0.125f;
        }
        sc[s] = e;
    }
    float mx = sc[0];
    #pragma unroll
    for (int s = 1; s < Kw; s++) mx = fmaxf(mx, sc[s]);

    float denom = 0.f;
    __half2 oa[4];
    #pragma unroll
    for (int i = 0; i < 4; i++) oa[i] = __floats2half2_rn(0.f, 0.f);

    #pragma unroll
    for (int s = 0; s < Kw; s++) {
        if (s < nv) {
            float wgt = __expf(sc[s] - mx);
            denom += wgt;
            __half2 wh = __float2half2_rn(wgt);
            int r = q - s * DIL - jlo;
            uint4 vv4 = *(const uint4*)&sv[r * HDm + l8 * 8];
            const __half2* vh = (const __half2*)&vv4;
            #pragma unroll
            for (int i = 0; i < 4; i++)
                oa[i] = __hfma2(wh, vh[i], oa[i]);
        }
    }
    __half2 rh = __float2half2_rn(1.0f / denom);
    __half2 oh[4];
    #pragma unroll
    for (int i = 0; i < 4; i++)
        oh[i] = __hmul2(oa[i], rh);
    *(uint4*)(o + ((size_t)(b * Tsz + q)) * Dsz + h * HDm + l8 * 8) = *(uint4*)oh;
}

// ---------------- fp16 mma.sync GEMM, S-stage cp.async pipeline ----------------------
// C[M,N] = A[M,K] @ Bt[N,K]^T.  128 x BN_ x BK tile, 256 threads (8 warps: 4M x 2N).
// EPI: 0 = store half, 1 = +bias + exact GELU -> half, 2 = +bias + residual -> float
template <int BN_, int EPI, int BK, int S, int MINCTAS>
__global__ void __launch_bounds__(256, MINCTAS)
mma_gemm(const __half* __restrict__ A, const __half* __restrict__ Bt,
         const float* __restrict__ bias, const float* __restrict__ res,
         void* __restrict__ Cv, int N, int K) {
    constexpr int BM = 128;
    constexpr int RST = BK + 8;
    constexpr int ABYTES = BM * RST * 2;
    constexpr int BBYTES = BN_ * RST * 2;
    constexpr int WN = BN_ / 2;
    constexpr int NT = WN / 8;
    constexpr int NPAIR = NT / 2;
    constexpr int AITER = (BM * BK / 8) / 256;
    constexpr int BITER = (BN_ * BK / 8) / 256;
    constexpr int KSTEPS = BK / 16;

    extern __shared__ char dsm[];
    const uint32_t sbase = smem_u32(dsm);
    const uint32_t bbase = sbase + S * ABYTES;

    const int tid  = threadIdx.x;
    const int w    = tid >> 5, lane = tid & 31;
    const int wm   = w & 3,   wn   = w >> 2;
    const int g    = lane >> 2, t4 = lane & 3;
    const int quad = lane >> 3, qr = lane & 7;
    const int bx   = blockIdx.x * BN_, by = blockIdx.y * BM;

    const __half* Ag[AITER]; uint32_t Asm[AITER];
    #pragma unroll
    for (int i = 0; i < AITER; i++) {
        int e = tid + i * 256, row = e / (BK / 8), seg = e % (BK / 8);
        Ag[i]  = A + (size_t)(by + row) * K + seg * 8;
        Asm[i] = sbase + (row * RST + seg * 8) * 2;
    }
    const __half* Bg[BITER]; uint32_t Bsm[BITER];
    #pragma unroll
    for (int i = 0; i < BITER; i++) {
        int e = tid + i * 256, row = e / (BK / 8), seg = e % (BK / 8);
        Bg[i]  = Bt + (size_t)(bx + row) * K + seg * 8;
        Bsm[i] = bbase + (row * RST + seg * 8) * 2;
    }

    uint32_t aAddr[2], bAddr[NPAIR];
    #pragma unroll
    for (int mt = 0; mt < 2; mt++) {
        int row = wm * 32 + mt * 16 + (quad & 1) * 8 + qr;
        int col = (quad >> 1) * 8;
        aAddr[mt] = sbase + (row * RST + col) * 2;
    }
    #pragma unroll
    for (int p = 0; p < NPAIR; p++) {
        int row = wn * WN + p * 16 + (quad & 1) * 8 + qr;
        int col = (quad >> 1) * 8;
        bAddr[p] = bbase + (row * RST + col) * 2;
    }

    float acc[2][NT][4];
    #pragma unroll
    for (int i = 0; i < 2; i++)
        #pragma unroll
        for (int j = 0; j < NT; j++)
            #pragma unroll
            for (int q = 0; q < 4; q++) acc[i][j][q] = 0.f;

    const int nch = K / BK;

    #pragma unroll
    for (int s = 0; s < S - 1; s++) {
        const int ko = s * BK;
        #pragma unroll
        for (int i = 0; i < AITER; i++) cp16(Asm[i] + s * ABYTES, Ag[i] + ko);
        #pragma unroll
        for (int i = 0; i < BITER; i++) cp16(Bsm[i] + s * BBYTES, Bg[i] + ko);
        asm volatile("cp.async.commit_group;");
    }

    int cst = 0;
    int lst = S - 1;

    for (int c = 0; c < nch; ++c) {
        asm volatile("cp.async.wait_group %0;" :: "n"(S - 2));
        __syncthreads();

        const int ls = c + S - 1;
        if (ls < nch) {
            const int ko = ls * BK;
            #pragma unroll
            for (int i = 0; i < AITER; i++) cp16(Asm[i] + lst * ABYTES, Ag[i] + ko);
            #pragma unroll
            for (int i = 0; i < BITER; i++) cp16(Bsm[i] + lst * BBYTES, Bg[i] + ko);
        }
        asm volatile("cp.async.commit_group;");

        const uint32_t aOff = cst * ABYTES;
        const uint32_t bOff = cst * BBYTES;
        #pragma unroll
        for (int ks = 0; ks < KSTEPS; ks++) {
            const uint32_t kb = ks * 32;
            uint32_t af[2][4];
            #pragma unroll
            for (int mt = 0; mt < 2; mt++) ldsm4(af[mt], aAddr[mt] + aOff + kb);
            uint32_t bf[NPAIR][4];
            #pragma unroll
            for (int p = 0; p < NPAIR; p++) ldsm4(bf[p], bAddr[p] + bOff + kb);
            #pragma unroll
            for (int mt = 0; mt < 2; mt++)
                #pragma unroll
                for (int p = 0; p < NPAIR; p++) {
                    uint32_t b0[2] = { bf[p][0], bf[p][2] };
                    uint32_t b1[2] = { bf[p][1], bf[p][3] };
                    mma_f16(acc[mt][2 * p],     af[mt], b0);
                    mma_f16(acc[mt][2 * p + 1], af[mt], b1);
                }
        }
        cst = (cst == S - 1) ? 0 : cst + 1;
        lst = (lst == S - 1) ? 0 : lst + 1;
    }

    #pragma unroll
    for (int mt = 0; mt < 2; mt++) {
        const int r0 = by + wm * 32 + mt * 16 + g;
        #pragma unroll
        for (int nt = 0; nt < NT; nt++) {
            const int col = bx + wn * WN + nt * 8 + 2 * t4;
            float v0 = acc[mt][nt][0], v1 = acc[mt][nt][1];
            float v2 = acc[mt][nt][2], v3 = acc[mt][nt][3];
            if (EPI != 0) {
                float2 bb = *(const float2*)&bias[col];
                v0 += bb.x; v1 += bb.y; v2 += bb.x; v3 += bb.y;
            }
            if (EPI == 1) {
                v0 = 0.5f * v0 * (1.0f + erff(v0 * 0.70710678118654752f));
                v1 = 0.5f * v1 * (1.0f + erff(v1 * 0.70710678118654752f));
                v2 = 0.5f * v2 * (1.0f + erff(v2 * 0.70710678118654752f));
                v3 = 0.5f * v3 * (1.0f + erff(v3 * 0.70710678118654752f));
            }
            if (EPI == 2) {
                float* C = (float*)Cv;
                float2 ra = *(const float2*)&res[(size_t)r0 * N + col];
                float2 rb = *(const float2*)&res[(size_t)(r0 + 8) * N + col];
                float2 o01 = { v0 + ra.x, v1 + ra.y };
                float2 o23 = { v2 + rb.x, v3 + rb.y };
                *(float2*)&C[(size_t)r0 * N + col]       = o01;
                *(float2*)&C[(size_t)(r0 + 8) * N + col] = o23;
            } else {
                __half* C = (__half*)Cv;
                *(__half2*)&C[(size_t)r0 * N + col]       = __floats2half2_rn(v0, v1);
                *(__half2*)&C[(size_t)(r0 + 8) * N + col] = __floats2half2_rn(v2, v3);
            }
        }
    }
}

// ---------------- launcher -----------------------------------------------------------
// BN=128: BK=64, S=3, 2 CTAs/SM -> 110592 bytes  [qkv, mlp1]
// BN=64 : BK=32, S=4, 3 CTAs/SM -> 61440  bytes  [proj, mlp2]
#define SMEM128  110592
#define SMEM64   61440

extern "C" void kernel_launch(void* const* d_in, const int* in_sizes, int n_in,
                              void* d_out, int out_size) {
    const float* x_in   = (const float*)d_in[0];
    const float* ln1_s  = (const float*)d_in[1];
    const float* ln1_b  = (const float*)d_in[2];
    const float* qkv_w  = (const float*)d_in[3];
    const float* proj_w = (const float*)d_in[4];
    const float* proj_b = (const float*)d_in[5];
    const float* ln2_s  = (const float*)d_in[6];
    const float* ln2_b  = (const float*)d_in[7];
    const float* w1     = (const float*)d_in[8];
    const float* b1     = (const float*)d_in[9];
    const float* w2     = (const float*)d_in[10];
    const float* b2     = (const float*)d_in[11];

    float* x = (float*)d_out;

    __half *h, *qkv, *o, *mlp, *qkvT, *projT, *w1T, *w2T;
    cudaGetSymbolAddress((void**)&h,     g_h);
    cudaGetSymbolAddress((void**)&qkv,   g_qkv);
    cudaGetSymbolAddress((void**)&o,     g_o);
    cudaGetSymbolAddress((void**)&mlp,   g_mlp);
    cudaGetSymbolAddress((void**)&qkvT,  g_qkvwT);
    cudaGetSymbolAddress((void**)&projT, g_projwT);
    cudaGetSymbolAddress((void**)&w1T,   g_w1T);
    cudaGetSymbolAddress((void**)&w2T,   g_w2T);

    cudaFuncSetAttribute((const void*)mma_gemm<128,0,64,3,2>, cudaFuncAttributeMaxDynamicSharedMemorySize, SMEM128);
    cudaFuncSetAttribute((const void*)mma_gemm<128,1,64,3,2>, cudaFuncAttributeMaxDynamicSharedMemorySize, SMEM128);
    cudaFuncSetAttribute((const void*)mma_gemm<64,2,32,4,3>,  cudaFuncAttributeMaxDynamicSharedMemorySize, SMEM64);

    // launches #1,#2: weight prep (keeps the qkv GEMM at launch #4 for profiling)
    prep_weights_a<<<NDEPTH * 1024, dim3(32, 8)>>>(qkv_w, proj_w);
    prep_weights_b<<<NDEPTH * 2048, dim3(32, 8)>>>(w1, w2);

    for (int d = 0; d < NDEPTH; d++) {
        const float* xr = (d == 0) ? x_in : x;

        ln_kernel<<<ROWS, 256>>>(xr, ln1_s + d * Dsz, ln1_b + d * Dsz, h);

        // qkv = h @ qkv_w   (4096 x 1536 x 512)
        mma_gemm<128,0,64,3,2><<<dim3((3 * Dsz) / 128, ROWS / 128), 256, SMEM128>>>(
            h, qkvT + (size_t)d * 3 * Dsz * Dsz, nullptr, nullptr, qkv, 3 * Dsz, Dsz);

        // sparse dilated attention
        dim3 agrid(Tsz / QT, Bsz * Hn);
        if (d == 0)      attn_kernel<1><<<agrid, 128>>>(qkv, o);
        else if (d == 1) attn_kernel<2><<<agrid, 128>>>(qkv, o);
        else             attn_kernel<4><<<agrid, 128>>>(qkv, o);

        // x = xr + o @ proj_w + proj_b   (4096 x 512 x 512)
        mma_gemm<64,2,32,4,3><<<dim3(Dsz / 64, ROWS / 128), 256, SMEM64>>>(
            o, projT + (size_t)d * Dsz * Dsz, proj_b + d * Dsz, xr, x, Dsz, Dsz);

        ln_kernel<<<ROWS, 256>>>(x, ln2_s + d * Dsz, ln2_b + d * Dsz, h);

        // mlp = gelu(h @ w1 + b1)   (4096 x 2048 x 512)
        mma_gemm<128,1,64,3,2><<<dim3((4 * Dsz) / 128, ROWS / 128), 256, SMEM128>>>(
            h, w1T + (size_t)d * Dsz * 4 * Dsz, b1 + (size_t)d * 4 * Dsz, nullptr,
            mlp, 4 * Dsz, Dsz);

        // x = x + mlp @ w2 + b2   (4096 x 512 x 2048)
        mma_gemm<64,2,32,4,3><<<dim3(Dsz / 64, ROWS / 128), 256, SMEM64>>>(
            mlp, w2T + (size_t)d * Dsz * 4 * Dsz, b2 + d * Dsz, x, x, Dsz, 4 * Dsz);
    }
}

// round 15
// speedup vs baseline: 1.1238x; 1.0684x over previous
#include <cuda_runtime.h>
#include <cuda_fp16.h>
#include <math.h>
#include <stdint.h>

#define Bsz   2
#define Tsz   2048
#define Dsz   512
#define Hn    8
#define HDm   64
#define Kw    16
#define NDEPTH 3
#define ROWS  (Bsz*Tsz)   // 4096

// ---------------- scratch (static device globals; no allocation) ----------------
__device__ __half g_h[ROWS * Dsz];
__device__ __half g_qkv[ROWS * 3 * Dsz];
__device__ __half g_o[ROWS * Dsz];
__device__ __half g_mlp[ROWS * 4 * Dsz];
// transposed fp16 weights ([N,K], K contiguous)
__device__ __half g_qkvwT[NDEPTH * 3 * Dsz * Dsz];
__device__ __half g_projwT[NDEPTH * Dsz * Dsz];
__device__ __half g_w1T[NDEPTH * 4 * Dsz * Dsz];
__device__ __half g_w2T[NDEPTH * Dsz * 4 * Dsz];

// ---------------- helpers ----------------------------------------------------------
__device__ __forceinline__ uint32_t smem_u32(const void* p) {
    uint32_t a;
    asm("{ .reg .u64 t; cvta.to.shared.u64 t, %1; cvt.u32.u64 %0, t; }" : "=r"(a) : "l"(p));
    return a;
}
__device__ __forceinline__ void cp16(uint32_t s, const void* g) {
    asm volatile("cp.async.cg.shared.global [%0], [%1], 16;" :: "r"(s), "l"(g));
}
__device__ __forceinline__ void ldsm4(uint32_t* r, uint32_t addr) {
    asm volatile("ldmatrix.sync.aligned.m8n8.x4.shared.b16 {%0,%1,%2,%3}, [%4];"
                 : "=r"(r[0]), "=r"(r[1]), "=r"(r[2]), "=r"(r[3]) : "r"(addr));
}
__device__ __forceinline__ void mma_f16(float* c, const uint32_t* a, const uint32_t* b) {
    asm volatile(
        "mma.sync.aligned.m16n8k16.row.col.f32.f16.f16.f32 "
        "{%0,%1,%2,%3}, {%4,%5,%6,%7}, {%8,%9}, {%0,%1,%2,%3};"
        : "+f"(c[0]), "+f"(c[1]), "+f"(c[2]), "+f"(c[3])
        : "r"(a[0]), "r"(a[1]), "r"(a[2]), "r"(a[3]), "r"(b[0]), "r"(b[1]));
}
// tanh-form GELU with HW MUFU.TANH (|x| < ~2.5 here -> abs err ~2-5e-4)
__device__ __forceinline__ float gelu_fast(float v) {
    float u = v * (0.7978845608028654f + 0.03567740813636141f * v * v);
    float t;
    asm("tanh.approx.f32 %0, %1;" : "=f"(t) : "f"(u));
    return 0.5f * v * (1.0f + t);
}

// ---------------- weight prep (split in two launches for profiling order) -----------
__device__ __forceinline__ void tr_tile(const float* in, __half* out, int R, int C, int t0) {
    __shared__ float tile[32][33];
    int tpc = C / 32;
    int r0 = (t0 / tpc) * 32, c0 = (t0 % tpc) * 32;
    int tx = threadIdx.x, ty = threadIdx.y;   // (32, 8)
    #pragma unroll
    for (int i = 0; i < 32; i += 8)
        tile[ty + i][tx] = in[(size_t)(r0 + ty + i) * C + c0 + tx];
    __syncthreads();
    #pragma unroll
    for (int i = 0; i < 32; i += 8)
        out[(size_t)(c0 + ty + i) * R + r0 + tx] = __float2half(tile[tx][ty + i]);
}

__global__ void prep_weights_a(const float* __restrict__ qkv_w, const float* __restrict__ proj_w) {
    int id = blockIdx.x;
    int d  = id / 1024;
    int r  = id % 1024;
    if (r < 768) tr_tile(qkv_w  + (size_t)d * Dsz * 3 * Dsz, g_qkvwT  + (size_t)d * 3 * Dsz * Dsz, Dsz, 3 * Dsz, r);
    else         tr_tile(proj_w + (size_t)d * Dsz * Dsz,     g_projwT + (size_t)d * Dsz * Dsz,     Dsz, Dsz,     r - 768);
}

__global__ void prep_weights_b(const float* __restrict__ w1, const float* __restrict__ w2) {
    int id = blockIdx.x;
    int d  = id / 2048;
    int r  = id % 2048;
    if (r < 1024) tr_tile(w1 + (size_t)d * Dsz * 4 * Dsz, g_w1T + (size_t)d * 4 * Dsz * Dsz, Dsz,     4 * Dsz, r);
    else          tr_tile(w2 + (size_t)d * 4 * Dsz * Dsz, g_w2T + (size_t)d * Dsz * 4 * Dsz, 4 * Dsz, Dsz,     r - 1024);
}

// ---------------- LayerNorm: one warp per row, 8 rows/block, float4 I/O -------------
__global__ void __launch_bounds__(256)
ln_kernel(const float* __restrict__ x, const float* __restrict__ s,
          const float* __restrict__ b, __half* __restrict__ out) {
    const int w = threadIdx.x >> 5, lane = threadIdx.x & 31;
    const int row = blockIdx.x * 8 + w;

    const float4* xr = (const float4*)(x + (size_t)row * Dsz);   // 128 float4/row
    float4 v[4];
    float a = 0.f, q = 0.f;
    #pragma unroll
    for (int i = 0; i < 4; i++) {
        v[i] = xr[lane + 32 * i];
        a += v[i].x + v[i].y + v[i].z + v[i].w;
        q += v[i].x * v[i].x + v[i].y * v[i].y + v[i].z * v[i].z + v[i].w * v[i].w;
    }
    #pragma unroll
    for (int m = 16; m; m >>= 1) {
        a += __shfl_xor_sync(0xffffffffu, a, m);
        q += __shfl_xor_sync(0xffffffffu, q, m);
    }
    float mean = a * (1.0f / Dsz);
    float inv  = rsqrtf(q * (1.0f / Dsz) - mean * mean + 1e-5f);

    const float4* s4 = (const float4*)s;
    const float4* b4 = (const float4*)b;
    uint2* orow = (uint2*)(out + (size_t)row * Dsz);   // 8 bytes per float4 group
    #pragma unroll
    for (int i = 0; i < 4; i++) {
        float4 sv = s4[lane + 32 * i];
        float4 bv = b4[lane + 32 * i];
        float o0 = (v[i].x - mean) * inv * sv.x + bv.x;
        float o1 = (v[i].y - mean) * inv * sv.y + bv.y;
        float o2 = (v[i].z - mean) * inv * sv.z + bv.z;
        float o3 = (v[i].w - mean) * inv * sv.w + bv.w;
        __half2 h0 = __floats2half2_rn(o0, o1);
        __half2 h1 = __floats2half2_rn(o2, o3);
        uint2 u = { *(uint32_t*)&h0, *(uint32_t*)&h1 };
        orow[lane + 32 * i] = u;
    }
}

// ---------------- Dilated sparse attention: QT=16 queries/block, 128 threads --------
// fp16x2 inner math (round-14): score dot via __hfma2, half2 V accumulators.
#define QT 16
template <int DIL>
__global__ void __launch_bounds__(128)
attn_kernel(const __half* __restrict__ qkv, __half* __restrict__ o) {
    constexpr int NR = QT + (Kw - 1) * DIL;
    __shared__ __half sk[NR * HDm];
    __shared__ __half sv[NR * HDm];

    const int tid = threadIdx.x;
    const int b   = blockIdx.y >> 3;
    const int h   = blockIdx.y & 7;
    const int q0  = blockIdx.x * QT;

    const int jlo   = max(0, q0 - (Kw - 1) * DIL);
    const int nrows = q0 + QT - jlo;

    const __half* kvbase = qkv + ((size_t)(b * Tsz + jlo)) * (3 * Dsz) + h * HDm;
    for (int idx = tid; idx < nrows * 8; idx += 128) {
        int row = idx >> 3, seg = idx & 7;
        const __half* src = kvbase + (size_t)row * (3 * Dsz) + seg * 8;
        *(uint4*)&sk[row * HDm + seg * 8] = *(const uint4*)(src + Dsz);
        *(uint4*)&sv[row * HDm + seg * 8] = *(const uint4*)(src + 2 * Dsz);
    }
    __syncthreads();

    const int l8 = tid & 7;
    const int q  = q0 + (tid >> 3);

    uint4 qv = *(const uint4*)(qkv + ((size_t)(b * Tsz + q)) * (3 * Dsz) + h * HDm + l8 * 8);
    const __half2* qh = (const __half2*)&qv;

    int nv = q / DIL + 1;
    if (nv > Kw) nv = Kw;

    float sc[Kw];
    #pragma unroll
    for (int s = 0; s < Kw; s++) {
        float e = -1e30f;
        if (s < nv) {
            int r = q - s * DIL - jlo;
            uint4 kv4 = *(const uint4*)&sk[r * HDm + l8 * 8];
            const __half2* kh = (const __half2*)&kv4;
            __half2 ph = __hmul2(qh[0], kh[0]);
            ph = __hfma2(qh[1], kh[1], ph);
            ph = __hfma2(qh[2], kh[2], ph);
            ph = __hfma2(qh[3], kh[3], ph);
            float p = __half2float(__low2half(ph)) + __half2float(__high2half(ph));
            p += __shfl_xor_sync(0xffffffffu, p, 4);
            p += __shfl_xor_sync(0xffffffffu, p, 2);
            p += __shfl_xor_sync(0xffffffffu, p, 1);
            e = p * 0.125f;
        }
        sc[s] = e;
    }
    float mx = sc[0];
    #pragma unroll
    for (int s = 1; s < Kw; s++) mx = fmaxf(mx, sc[s]);

    float denom = 0.f;
    __half2 oa[4];
    #pragma unroll
    for (int i = 0; i < 4; i++) oa[i] = __floats2half2_rn(0.f, 0.f);

    #pragma unroll
    for (int s = 0; s < Kw; s++) {
        if (s < nv) {
            float wgt = __expf(sc[s] - mx);
            denom += wgt;
            __half2 wh = __float2half2_rn(wgt);
            int r = q - s * DIL - jlo;
            uint4 vv4 = *(const uint4*)&sv[r * HDm + l8 * 8];
            const __half2* vh = (const __half2*)&vv4;
            #pragma unroll
            for (int i = 0; i < 4; i++)
                oa[i] = __hfma2(wh, vh[i], oa[i]);
        }
    }
    __half2 rh = __float2half2_rn(1.0f / denom);
    __half2 oh[4];
    #pragma unroll
    for (int i = 0; i < 4; i++)
        oh[i] = __hmul2(oa[i], rh);
    *(uint4*)(o + ((size_t)(b * Tsz + q)) * Dsz + h * HDm + l8 * 8) = *(uint4*)oh;
}

// ---------------- fp16 mma.sync GEMM, S-stage cp.async pipeline ----------------------
// C[M,N] = A[M,K] @ Bt[N,K]^T.  128 x BN_ x BK tile, 256 threads (8 warps: 4M x 2N).
// EPI: 0 = store half, 1 = +bias + GELU(tanh/MUFU) -> half, 2 = +bias + residual -> float
template <int BN_, int EPI, int BK, int S, int MINCTAS>
__global__ void __launch_bounds__(256, MINCTAS)
mma_gemm(const __half* __restrict__ A, const __half* __restrict__ Bt,
         const float* __restrict__ bias, const float* __restrict__ res,
         void* __restrict__ Cv, int N, int K) {
    constexpr int BM = 128;
    constexpr int RST = BK + 8;
    constexpr int ABYTES = BM * RST * 2;
    constexpr int BBYTES = BN_ * RST * 2;
    constexpr int WN = BN_ / 2;
    constexpr int NT = WN / 8;
    constexpr int NPAIR = NT / 2;
    constexpr int AITER = (BM * BK / 8) / 256;
    constexpr int BITER = (BN_ * BK / 8) / 256;
    constexpr int KSTEPS = BK / 16;

    extern __shared__ char dsm[];
    const uint32_t sbase = smem_u32(dsm);
    const uint32_t bbase = sbase + S * ABYTES;

    const int tid  = threadIdx.x;
    const int w    = tid >> 5, lane = tid & 31;
    const int wm   = w & 3,   wn   = w >> 2;
    const int g    = lane >> 2, t4 = lane & 3;
    const int quad = lane >> 3, qr = lane & 7;
    const int bx   = blockIdx.x * BN_, by = blockIdx.y * BM;

    const __half* Ag[AITER]; uint32_t Asm[AITER];
    #pragma unroll
    for (int i = 0; i < AITER; i++) {
        int e = tid + i * 256, row = e / (BK / 8), seg = e % (BK / 8);
        Ag[i]  = A + (size_t)(by + row) * K + seg * 8;
        Asm[i] = sbase + (row * RST + seg * 8) * 2;
    }
    const __half* Bg[BITER]; uint32_t Bsm[BITER];
    #pragma unroll
    for (int i = 0; i < BITER; i++) {
        int e = tid + i * 256, row = e / (BK / 8), seg = e % (BK / 8);
        Bg[i]  = Bt + (size_t)(bx + row) * K + seg * 8;
        Bsm[i] = bbase + (row * RST + seg * 8) * 2;
    }

    uint32_t aAddr[2], bAddr[NPAIR];
    #pragma unroll
    for (int mt = 0; mt < 2; mt++) {
        int row = wm * 32 + mt * 16 + (quad & 1) * 8 + qr;
        int col = (quad >> 1) * 8;
        aAddr[mt] = sbase + (row * RST + col) * 2;
    }
    #pragma unroll
    for (int p = 0; p < NPAIR; p++) {
        int row = wn * WN + p * 16 + (quad & 1) * 8 + qr;
        int col = (quad >> 1) * 8;
        bAddr[p] = bbase + (row * RST + col) * 2;
    }

    float acc[2][NT][4];
    #pragma unroll
    for (int i = 0; i < 2; i++)
        #pragma unroll
        for (int j = 0; j < NT; j++)
            #pragma unroll
            for (int q = 0; q < 4; q++) acc[i][j][q] = 0.f;

    const int nch = K / BK;

    #pragma unroll
    for (int s = 0; s < S - 1; s++) {
        const int ko = s * BK;
        #pragma unroll
        for (int i = 0; i < AITER; i++) cp16(Asm[i] + s * ABYTES, Ag[i] + ko);
        #pragma unroll
        for (int i = 0; i < BITER; i++) cp16(Bsm[i] + s * BBYTES, Bg[i] + ko);
        asm volatile("cp.async.commit_group;");
    }

    int cst = 0;
    int lst = S - 1;

    for (int c = 0; c < nch; ++c) {
        asm volatile("cp.async.wait_group %0;" :: "n"(S - 2));
        __syncthreads();

        const int ls = c + S - 1;
        if (ls < nch) {
            const int ko = ls * BK;
            #pragma unroll
            for (int i = 0; i < AITER; i++) cp16(Asm[i] + lst * ABYTES, Ag[i] + ko);
            #pragma unroll
            for (int i = 0; i < BITER; i++) cp16(Bsm[i] + lst * BBYTES, Bg[i] + ko);
        }
        asm volatile("cp.async.commit_group;");

        const uint32_t aOff = cst * ABYTES;
        const uint32_t bOff = cst * BBYTES;
        #pragma unroll
        for (int ks = 0; ks < KSTEPS; ks++) {
            const uint32_t kb = ks * 32;
            uint32_t af[2][4];
            #pragma unroll
            for (int mt = 0; mt < 2; mt++) ldsm4(af[mt], aAddr[mt] + aOff + kb);
            uint32_t bf[NPAIR][4];
            #pragma unroll
            for (int p = 0; p < NPAIR; p++) ldsm4(bf[p], bAddr[p] + bOff + kb);
            #pragma unroll
            for (int mt = 0; mt < 2; mt++)
                #pragma unroll
                for (int p = 0; p < NPAIR; p++) {
                    uint32_t b0[2] = { bf[p][0], bf[p][2] };
                    uint32_t b1[2] = { bf[p][1], bf[p][3] };
                    mma_f16(acc[mt][2 * p],     af[mt], b0);
                    mma_f16(acc[mt][2 * p + 1], af[mt], b1);
                }
        }
        cst = (cst == S - 1) ? 0 : cst + 1;
        lst = (lst == S - 1) ? 0 : lst + 1;
    }

    #pragma unroll
    for (int mt = 0; mt < 2; mt++) {
        const int r0 = by + wm * 32 + mt * 16 + g;
        #pragma unroll
        for (int nt = 0; nt < NT; nt++) {
            const int col = bx + wn * WN + nt * 8 + 2 * t4;
            float v0 = acc[mt][nt][0], v1 = acc[mt][nt][1];
            float v2 = acc[mt][nt][2], v3 = acc[mt][nt][3];
            if (EPI != 0) {
                float2 bb = *(const float2*)&bias[col];
                v0 += bb.x; v1 += bb.y; v2 += bb.x; v3 += bb.y;
            }
            if (EPI == 1) {
                v0 = gelu_fast(v0);
                v1 = gelu_fast(v1);
                v2 = gelu_fast(v2);
                v3 = gelu_fast(v3);
            }
            if (EPI == 2) {
                float* C = (float*)Cv;
                float2 ra = *(const float2*)&res[(size_t)r0 * N + col];
                float2 rb = *(const float2*)&res[(size_t)(r0 + 8) * N + col];
                float2 o01 = { v0 + ra.x, v1 + ra.y };
                float2 o23 = { v2 + rb.x, v3 + rb.y };
                *(float2*)&C[(size_t)r0 * N + col]       = o01;
                *(float2*)&C[(size_t)(r0 + 8) * N + col] = o23;
            } else {
                __half* C = (__half*)Cv;
                *(__half2*)&C[(size_t)r0 * N + col]       = __floats2half2_rn(v0, v1);
                *(__half2*)&C[(size_t)(r0 + 8) * N + col] = __floats2half2_rn(v2, v3);
            }
        }
    }
}

// ---------------- launcher -----------------------------------------------------------
// BN=128: BK=64, S=3, 2 CTAs/SM -> 110592 bytes  [qkv, mlp1]
// BN=64 : BK=32, S=4, 3 CTAs/SM -> 61440  bytes  [proj, mlp2]
#define SMEM128  110592
#define SMEM64   61440

extern "C" void kernel_launch(void* const* d_in, const int* in_sizes, int n_in,
                              void* d_out, int out_size) {
    const float* x_in   = (const float*)d_in[0];
    const float* ln1_s  = (const float*)d_in[1];
    const float* ln1_b  = (const float*)d_in[2];
    const float* qkv_w  = (const float*)d_in[3];
    const float* proj_w = (const float*)d_in[4];
    const float* proj_b = (const float*)d_in[5];
    const float* ln2_s  = (const float*)d_in[6];
    const float* ln2_b  = (const float*)d_in[7];
    const float* w1     = (const float*)d_in[8];
    const float* b1     = (const float*)d_in[9];
    const float* w2     = (const float*)d_in[10];
    const float* b2     = (const float*)d_in[11];

    float* x = (float*)d_out;

    __half *h, *qkv, *o, *mlp, *qkvT, *projT, *w1T, *w2T;
    cudaGetSymbolAddress((void**)&h,     g_h);
    cudaGetSymbolAddress((void**)&qkv,   g_qkv);
    cudaGetSymbolAddress((void**)&o,     g_o);
    cudaGetSymbolAddress((void**)&mlp,   g_mlp);
    cudaGetSymbolAddress((void**)&qkvT,  g_qkvwT);
    cudaGetSymbolAddress((void**)&projT, g_projwT);
    cudaGetSymbolAddress((void**)&w1T,   g_w1T);
    cudaGetSymbolAddress((void**)&w2T,   g_w2T);

    cudaFuncSetAttribute((const void*)mma_gemm<128,0,64,3,2>, cudaFuncAttributeMaxDynamicSharedMemorySize, SMEM128);
    cudaFuncSetAttribute((const void*)mma_gemm<128,1,64,3,2>, cudaFuncAttributeMaxDynamicSharedMemorySize, SMEM128);
    cudaFuncSetAttribute((const void*)mma_gemm<64,2,32,4,3>,  cudaFuncAttributeMaxDynamicSharedMemorySize, SMEM64);

    // launches #1,#2: weight prep (keeps the qkv GEMM at launch #4 for profiling)
    prep_weights_a<<<NDEPTH * 1024, dim3(32, 8)>>>(qkv_w, proj_w);
    prep_weights_b<<<NDEPTH * 2048, dim3(32, 8)>>>(w1, w2);

    for (int d = 0; d < NDEPTH; d++) {
        const float* xr = (d == 0) ? x_in : x;

        ln_kernel<<<ROWS / 8, 256>>>(xr, ln1_s + d * Dsz, ln1_b + d * Dsz, h);

        // qkv = h @ qkv_w   (4096 x 1536 x 512)
        mma_gemm<128,0,64,3,2><<<dim3((3 * Dsz) / 128, ROWS / 128), 256, SMEM128>>>(
            h, qkvT + (size_t)d * 3 * Dsz * Dsz, nullptr, nullptr, qkv, 3 * Dsz, Dsz);

        // sparse dilated attention
        dim3 agrid(Tsz / QT, Bsz * Hn);
        if (d == 0)      attn_kernel<1><<<agrid, 128>>>(qkv, o);
        else if (d == 1) attn_kernel<2><<<agrid, 128>>>(qkv, o);
        else             attn_kernel<4><<<agrid, 128>>>(qkv, o);

        // x = xr + o @ proj_w + proj_b   (4096 x 512 x 512)
        mma_gemm<64,2,32,4,3><<<dim3(Dsz / 64, ROWS / 128), 256, SMEM64>>>(
            o, projT + (size_t)d * Dsz * Dsz, proj_b + d * Dsz, xr, x, Dsz, Dsz);

        ln_kernel<<<ROWS / 8, 256>>>(x, ln2_s + d * Dsz, ln2_b + d * Dsz, h);

        // mlp = gelu(h @ w1 + b1)   (4096 x 2048 x 512)
        mma_gemm<128,1,64,3,2><<<dim3((4 * Dsz) / 128, ROWS / 128), 256, SMEM128>>>(
            h, w1T + (size_t)d * Dsz * 4 * Dsz, b1 + (size_t)d * 4 * Dsz, nullptr,
            mlp, 4 * Dsz, Dsz);

        // x = x + mlp @ w2 + b2   (4096 x 512 x 2048)
        mma_gemm<64,2,32,4,3><<<dim3(Dsz / 64, ROWS / 128), 256, SMEM64>>>(
            mlp, w2T + (size_t)d * Dsz * 4 * Dsz, b2 + d * Dsz, x, x, Dsz, 4 * Dsz);
    }
}